// round 17
// baseline (speedup 1.0000x reference)
#include <cuda_runtime.h>

// Ball query: build + PDL query, TWO warps per query (64-thread blocks).
// N1=4096 queries, N2=16384 refs, K=32, r=0.08, points uniform [0,1)^3.
//
// R17 vs R16 (wall 15.1, query kernel 12.06us):
//  - Query: 4096 blocks x 64 threads, one query per block, 2 warps split the
//    9 neighborhood rows (r = half, half+2, ...). __syncthreads IS the pair
//    barrier (no cross-query coupling, no named barriers). Per-warp serial
//    scan path ~halves. Duplicated prologue rides free under the PDL overlap.
//  - Build: 128 blocks x 128 threads; p2 read via shared staging (3 coalesced
//    loads, conflict-free stride-3 readback) instead of stride-12 LDGs.
//
// Replay-safe: per-kernel monotone tickets (tickA/128 == tickB/4096 = call),
// generation-parity double-buffered counters (g_n[par] built this call,
// g_n[1-par] zeroed for next call; first call covered by .bss zeros).
// Deterministic: hits ranked by unique original index.
//
// Hit predicate bit-identical to verified formula (rel_err 0.0 x14):
//   s = ((x*x + y*y) + z*z)  (mul/add, no fma contraction)
//   dot = fmaf(z1,z2, fmaf(y1,y2, x1*x2))
//   d2  = (s1 + s2) - 2*dot;  hit iff d2 <= r^2

#define BQ_N1 4096
#define BQ_N2 16384
#define BQ_K 32
#define BQ_R2 0.0064f
#define BQ_R2P 0.00641f
#define BQ_G 12
#define BQ_NC (BQ_G * BQ_G * BQ_G)  // 1728
#define BQ_CAP 48
#define BQ_BUF 128
#define NBLK_A 128                  // build: 128*128 = 16384 threads
#define NBLK_B 4096                 // query: one block (2 warps) per query

__device__ unsigned g_tickA;            // build-kernel call tickets
__device__ unsigned g_tickB;            // query-kernel call tickets
__device__ int g_n[2][BQ_NC];           // parity-double-buffered counts
__device__ float4 g_cp[BQ_NC * BQ_CAP]; // x, y, z, idx_bits

__device__ __forceinline__ int cell1(float v) {
    int c = (int)(v * (float)BQ_G);
    return c < 0 ? 0 : (c > BQ_G - 1 ? BQ_G - 1 : c);
}

// ---- Primary: zero(next parity) + direct bin, coalesced p2 read ----
__global__ __launch_bounds__(128) void bq_build(const float* __restrict__ p2) {
    __shared__ float sp[384];   // 128 points * 3 floats, staged coalesced
    __shared__ unsigned s_call;
    int tid = threadIdx.x;
    int base = blockIdx.x * 128;

    if (tid == 0) s_call = atomicAdd(&g_tickA, 1u) / NBLK_A;

    // 3 coalesced 128-float loads.
    const float* src = p2 + (size_t)base * 3;
    sp[tid] = src[tid];
    sp[tid + 128] = src[tid + 128];
    sp[tid + 256] = src[tid + 256];
    __syncthreads();

    int par = (int)(s_call & 1u);
    int gid = base + tid;

    // Zero the OTHER parity buffer for the next call (no reader exists now).
    if (gid < BQ_NC) g_n[1 - par][gid] = 0;

    // Stride-3 readback: 3 coprime 32 -> conflict-free.
    float px = sp[3 * tid + 0];
    float py = sp[3 * tid + 1];
    float pz = sp[3 * tid + 2];
    int c = (cell1(pz) * BQ_G + cell1(py)) * BQ_G + cell1(px);
    int slot = atomicAdd(&g_n[par][c], 1);
    if (slot < BQ_CAP)
        g_cp[c * BQ_CAP + slot] = make_float4(px, py, pz, __int_as_float(gid));
}

// ---- Secondary (PDL): one query per 64-thread block, 2 warps split rows ----
__global__ __launch_bounds__(64) void bq_query(const float* __restrict__ p1,
                                               float* __restrict__ out) {
    __shared__ int keyb[BQ_BUF];      // packed hit records
    __shared__ float ob[BQ_K * 4];    // staged outputs
    __shared__ int s_wcnt;
    __shared__ unsigned s_call;

    int tid = threadIdx.x;            // 0..63
    int half = tid >> 5;              // which row-half this warp scans
    int lane = tid & 31;
    int q = blockIdx.x;               // one query per block

    if (tid == 0) {
        s_call = atomicAdd(&g_tickB, 1u) / NBLK_B;
        s_wcnt = 0;
    }

    // Build-independent prologue (overlaps the primary kernel).
    ob[tid] = 0.0f;
    ob[64 + tid] = 0.0f;

    float x1 = p1[3 * q + 0];
    float y1 = p1[3 * q + 1];
    float z1 = p1[3 * q + 2];
    float s1 = __fadd_rn(__fadd_rn(__fmul_rn(x1, x1), __fmul_rn(y1, y1)),
                         __fmul_rn(z1, z1));
    int cx = cell1(x1), cy = cell1(y1), cz = cell1(z1);
    int xlo = cx > 0 ? cx - 1 : 0;
    int xhi = cx < BQ_G - 1 ? cx + 1 : BQ_G - 1;
    const float invG = 1.0f / (float)BQ_G;
    float dxl = x1 - (float)cx * invG, dxr = (float)(cx + 1) * invG - x1;
    float dyl = y1 - (float)cy * invG, dyr = (float)(cy + 1) * invG - y1;
    float dzl = z1 - (float)cz * invG, dzr = (float)(cz + 1) * invG - z1;
    float dxl2 = dxl * dxl, dxr2 = dxr * dxr;

    __syncthreads();  // s_call/s_wcnt/ob zeros visible to both warps
    int par = (int)(s_call & 1u);
    int* cnts = g_n[par];

    // Wait for the primary grid (build) to complete with memory visibility.
    asm volatile("griddepcontrol.wait;" ::: "memory");

    // ---- Scan: this warp handles rows r = half, half+2, ... ----
    for (int r = half; r < 9; r += 2) {
        int dzi = r / 3 - 1, dyi = r % 3 - 1;
        int zz = cz + dzi, yy = cy + dyi;
        if (zz < 0 || zz >= BQ_G || yy < 0 || yy >= BQ_G) continue;
        float ddz = (dzi < 0) ? dzl : ((dzi > 0) ? dzr : 0.0f);
        float ddy = (dyi < 0) ? dyl : ((dyi > 0) ? dyr : 0.0f);
        float dyz2 = ddz * ddz + ddy * ddy;
        if (dyz2 > BQ_R2P) continue;                   // row unreachable
        int xl = xlo, xh = xhi;
        if (xl < cx && dxl2 + dyz2 > BQ_R2P) xl = cx;  // left cell out
        if (xh > cx && dxr2 + dyz2 > BQ_R2P) xh = cx;  // right cell out
        int c0 = (zz * BQ_G + yy) * BQ_G + xl;
        int nc = xh - xl + 1;
        int n0 = min(cnts[c0], BQ_CAP);
        int n1 = (nc > 1) ? min(cnts[c0 + 1], BQ_CAP) : 0;
        int n2 = (nc > 2) ? min(cnts[c0 + 2], BQ_CAP) : 0;
        int t01 = n0 + n1;
        int tot = t01 + n2;
        int base0 = c0 * BQ_CAP;
        for (int t = lane; t < tot; t += 32) {
            int a = base0 + (t < n0 ? t
                    : (t < t01 ? BQ_CAP + t - n0 : 2 * BQ_CAP + t - t01));
            float4 p = g_cp[a];
            float s2 = __fadd_rn(
                __fadd_rn(__fmul_rn(p.x, p.x), __fmul_rn(p.y, p.y)),
                __fmul_rn(p.z, p.z));
            float dot = fmaf(z1, p.z, fmaf(y1, p.y, __fmul_rn(x1, p.x)));
            float d2 = __fsub_rn(__fadd_rn(s1, s2), __fmul_rn(2.0f, dot));
            if (d2 <= BQ_R2) {
                int pos = atomicAdd(&s_wcnt, 1);
                if (pos < BQ_BUF)
                    keyb[pos] = (__float_as_int(p.w) << 17) | a;
            }
        }
    }

    __syncthreads();  // pair barrier: both warps' appends visible
    int cnt = s_wcnt;

    // ---- 64-lane joint epilogue ----
    int cc = cnt < BQ_BUF ? cnt : BQ_BUF;
    // Rank by packed key (idx-major, idx unique) -> reference's "first K in
    // ascending original index" order, independent of append order.
    for (int e0 = tid; e0 < cc; e0 += 64) {
        int key = keyb[e0];
        int rank = 0;
        for (int i = 0; i < cc; i++) rank += (keyb[i] < key);
        if (rank < BQ_K) {
            float4 p = g_cp[key & 0x1FFFF];  // L1-hot reload
            ob[rank] = (float)(key >> 17);
            ob[32 + rank * 3 + 0] = p.x;
            ob[32 + rank * 3 + 1] = p.y;
            ob[32 + rank * 3 + 2] = p.z;
        }
    }
    __syncthreads();  // staged outputs complete

    float* mapping = out + (size_t)q * BQ_K;
    float* coords  = out + (size_t)BQ_N1 * BQ_K + BQ_N1 + (size_t)q * BQ_K * 3;
    if (tid < BQ_K) mapping[tid] = ob[tid];
    coords[tid] = ob[32 + tid];
    if (tid < BQ_K) coords[64 + tid] = ob[96 + tid];
    if (tid == 0)
        out[(size_t)BQ_N1 * BQ_K + q] = (float)(cnt < BQ_K ? cnt : BQ_K);
}

extern "C" void kernel_launch(void* const* d_in, const int* in_sizes, int n_in,
                              void* d_out, int out_size) {
    const float* p1 = (const float*)d_in[0];
    const float* p2 = (const float*)d_in[1];
    float* out = (float*)d_out;

    bq_build<<<NBLK_A, 128>>>(p2);

    cudaLaunchConfig_t cfg = {};
    cfg.gridDim = dim3(NBLK_B, 1, 1);
    cfg.blockDim = dim3(64, 1, 1);
    cfg.dynamicSmemBytes = 0;
    cfg.stream = 0;
    cudaLaunchAttribute attr[1];
    attr[0].id = cudaLaunchAttributeProgrammaticStreamSerialization;
    attr[0].val.programmaticStreamSerializationAllowed = 1;
    cfg.attrs = attr;
    cfg.numAttrs = 1;
    cudaLaunchKernelEx(&cfg, bq_query, p1, out);
}